// round 6
// baseline (speedup 1.0000x reference)
#include <cuda_runtime.h>
#include <cuda_fp16.h>
#include <math.h>
#include <stdint.h>

typedef unsigned long long ull;

// Problem constants
constexpr int N_PTS   = 65536;
constexpr int KP      = 15;
constexpr int IN_F    = 64;
constexpr int OUT_F   = 128;
constexpr int RDIM    = KP * IN_F;          // 960
constexpr float INV_EXT = 1.0f / 0.024f;
constexpr float BN_EPS  = 1e-6f;
constexpr float NEG_SLOPE = 0.1f;

constexpr int N_SLICES  = 2;
constexpr int SLICE_PTS = N_PTS / N_SLICES; // 32768

// Scratch
__device__ __half g_Ph[(size_t)N_PTS * RDIM];
__device__ __half g_Pl[(size_t)N_PTS * RDIM];
__device__ __half g_Whh[(size_t)RDIM * OUT_F];
__device__ __half g_Whl[(size_t)RDIM * OUT_F];
__device__ float g_psum[256 * OUT_F];
__device__ float g_psq [256 * OUT_F];
__device__ float g_scale[OUT_F];
__device__ float g_bias [OUT_F];

// ---- packed f32x2 helpers (K1) ----
__device__ __forceinline__ ull pk2(float lo, float hi) {
    ull r; asm("mov.b64 %0, {%1, %2};" : "=l"(r) : "f"(lo), "f"(hi)); return r;
}
__device__ __forceinline__ void up2(ull v, float& lo, float& hi) {
    asm("mov.b64 {%0, %1}, %2;" : "=f"(lo), "=f"(hi) : "l"(v));
}
__device__ __forceinline__ ull fma2(ull a, ull b, ull c) {
    ull d; asm("fma.rn.f32x2 %0, %1, %2, %3;" : "=l"(d) : "l"(a), "l"(b), "l"(c));
    return d;
}

__device__ __forceinline__ uint32_t smem_u32(const void* p) {
    uint32_t a;
    asm("{ .reg .u64 t; cvta.to.shared.u64 t, %1; cvt.u32.u64 %0, t; }" : "=r"(a) : "l"(p));
    return a;
}

// ---- mma.sync + cp.async helpers ----
__device__ __forceinline__ void ldmatrix_x4(uint32_t* r, uint32_t addr) {
    asm volatile("ldmatrix.sync.aligned.m8n8.x4.shared.b16 {%0,%1,%2,%3}, [%4];"
                 : "=r"(r[0]), "=r"(r[1]), "=r"(r[2]), "=r"(r[3]) : "r"(addr));
}
__device__ __forceinline__ void ldmatrix_x4_t(uint32_t* r, uint32_t addr) {
    asm volatile("ldmatrix.sync.aligned.m8n8.x4.trans.shared.b16 {%0,%1,%2,%3}, [%4];"
                 : "=r"(r[0]), "=r"(r[1]), "=r"(r[2]), "=r"(r[3]) : "r"(addr));
}
__device__ __forceinline__ void mma16816(float* c, const uint32_t* a,
                                         const uint32_t* b) {
    asm volatile(
        "mma.sync.aligned.m16n8k16.row.col.f32.f16.f16.f32 "
        "{%0,%1,%2,%3}, {%4,%5,%6,%7}, {%8,%9}, {%0,%1,%2,%3};"
        : "+f"(c[0]), "+f"(c[1]), "+f"(c[2]), "+f"(c[3])
        : "r"(a[0]), "r"(a[1]), "r"(a[2]), "r"(a[3]), "r"(b[0]), "r"(b[1]));
}
__device__ __forceinline__ void cp16(uint32_t saddr, const void* gptr) {
    asm volatile("cp.async.cg.shared.global [%0], [%1], 16;"
                 :: "r"(saddr), "l"(gptr) : "memory");
}
#define CP_COMMIT() asm volatile("cp.async.commit_group;" ::: "memory")
#define CP_WAIT(n)  asm volatile("cp.async.wait_group %0;" :: "n"(n) : "memory")

// =====================================================================
// K0: split W[k][o] -> fp16 hi/lo
// =====================================================================
__global__ __launch_bounds__(256) void k0_prep(const float* __restrict__ W) {
    const int idx = blockIdx.x * 256 + threadIdx.x;
    if (idx >= RDIM * OUT_F) return;
    const float w = W[idx];
    const __half hi = __float2half_rn(w);
    g_Whh[idx] = hi;
    g_Whl[idx] = __float2half_rn(w - __half2float(hi));
}

// =====================================================================
// K1: weighted features, fp16 hi/lo (sliced)
// =====================================================================
__global__ __launch_bounds__(256) void k1_weighted(
    const float* __restrict__ qp, const float* __restrict__ sp,
    const int*   __restrict__ nbr, const float* __restrict__ feat,
    const float* __restrict__ kpts, int rowOffset)
{
    __shared__ float kp_s[16][3];
    __shared__ float qp_s[16][3];
    __shared__ int   nbr_s[16][32];
    __shared__ float w_s[16][32][16];

    const int t = threadIdx.x;
    const int base = rowOffset + blockIdx.x * 16;

    if (t < 45) kp_s[t / 3][t % 3] = kpts[t];
    if (t >= 64 && t < 112) { int u = t - 64; qp_s[u / 3][u % 3] = qp[base * 3 + u]; }
    ((int*)nbr_s)[t]       = nbr[(size_t)base * 32 + t];
    ((int*)nbr_s)[t + 256] = nbr[(size_t)base * 32 + t + 256];
    __syncthreads();

    #pragma unroll
    for (int pair = t; pair < 512; pair += 256) {
        const int pt = pair >> 5, m = pair & 31;
        const int j = nbr_s[pt][m];
        const float dx = sp[(size_t)j * 3 + 0] - qp_s[pt][0];
        const float dy = sp[(size_t)j * 3 + 1] - qp_s[pt][1];
        const float dz = sp[(size_t)j * 3 + 2] - qp_s[pt][2];
        #pragma unroll
        for (int k = 0; k < KP; k++) {
            const float ax = dx - kp_s[k][0];
            const float ay = dy - kp_s[k][1];
            const float az = dz - kp_s[k][2];
            const float sq = ax * ax + ay * ay + az * az;
            w_s[pt][m][k] = fmaxf(1.0f - sqrtf(sq) * INV_EXT, 0.0f);
        }
        w_s[pt][m][15] = 0.0f;
    }
    __syncthreads();

    const int pt = t >> 4, lane = t & 15;
    const int gpt = base + pt;

    ull acc0[KP], acc1[KP];
    #pragma unroll
    for (int k = 0; k < KP; k++) { acc0[k] = 0ull; acc1[k] = 0ull; }

    int j0 = nbr_s[pt][0];
    float4 f = __ldg(reinterpret_cast<const float4*>(feat + (size_t)j0 * IN_F) + lane);

    #pragma unroll 2
    for (int m = 0; m < 32; m++) {
        float4 fn = f;
        if (m < 31) {
            const int jn = nbr_s[pt][m + 1];
            fn = __ldg(reinterpret_cast<const float4*>(feat + (size_t)jn * IN_F) + lane);
        }
        const ull fxy = pk2(f.x, f.y);
        const ull fzw = pk2(f.z, f.w);
        const float* wrow = w_s[pt][m];
        #pragma unroll
        for (int k = 0; k < KP; k++) {
            const float w = wrow[k];
            const ull wp = pk2(w, w);
            acc0[k] = fma2(wp, fxy, acc0[k]);
            acc1[k] = fma2(wp, fzw, acc1[k]);
        }
        f = fn;
    }

    const size_t rbase = (size_t)gpt * RDIM + lane * 4;
    #pragma unroll
    for (int k = 0; k < KP; k++) {
        float vx, vy, vz, vw;
        up2(acc0[k], vx, vy);
        up2(acc1[k], vz, vw);
        const __half hx = __float2half_rn(vx), hy = __float2half_rn(vy);
        const __half hz = __float2half_rn(vz), hw = __float2half_rn(vw);
        const __half lx = __float2half_rn(vx - __half2float(hx));
        const __half ly = __float2half_rn(vy - __half2float(hy));
        const __half lz = __float2half_rn(vz - __half2float(hz));
        const __half lw = __float2half_rn(vw - __half2float(hw));
        __half2* ph = reinterpret_cast<__half2*>(g_Ph + rbase + k * IN_F);
        __half2* pl = reinterpret_cast<__half2*>(g_Pl + rbase + k * IN_F);
        ph[0] = __halves2half2(hx, hy); ph[1] = __halves2half2(hz, hw);
        pl[0] = __halves2half2(lx, ly); pl[1] = __halves2half2(lz, lw);
    }
}

// =====================================================================
// K2 v2: cp.async 2-stage double-buffered fp16 3-term GEMM (sliced)
// =====================================================================
constexpr int SA = 40;    // A smem stride in halfs (conflict-free ldmatrix)
constexpr int SB = 136;   // B smem stride in halfs (conflict-free .trans)
constexpr int AH_BYTES = 128 * SA * 2;                    // 10240
constexpr int BH_BYTES = 32 * SB * 2;                     // 8704
constexpr int OFF_AL = AH_BYTES;                          // 10240
constexpr int OFF_BH = 2 * AH_BYTES;                      // 20480
constexpr int OFF_BL = 2 * AH_BYTES + BH_BYTES;           // 29184
constexpr int STAGE_BYTES = 2 * AH_BYTES + 2 * BH_BYTES;  // 37888
constexpr int K2_SMEM = 2 * STAGE_BYTES;                  // 75776

__device__ __forceinline__ void k2_load_chunk(
    uint32_t sbase, size_t rowBase, int k0, int tid)
{
    #pragma unroll
    for (int p = 0; p < 2; p++) {
        const int idx = p * 256 + tid;
        // A: 128 rows x 4 16B-cols
        const int row = idx >> 2, c = idx & 3;
        const size_t go = (rowBase + row) * RDIM + k0 + c * 8;
        const uint32_t sa = sbase + (uint32_t)(row * SA + c * 8) * 2;
        cp16(sa,          g_Ph + go);
        cp16(sa + OFF_AL, g_Pl + go);
        // B: 32 rows x 16 16B-cols
        const int brow = idx >> 4, bc = idx & 15;
        const size_t gb = (size_t)(k0 + brow) * OUT_F + bc * 8;
        const uint32_t sb = sbase + OFF_BH + (uint32_t)(brow * SB + bc * 8) * 2;
        cp16(sb,                    g_Whh + gb);
        cp16(sb + (OFF_BL - OFF_BH), g_Whl + gb);
    }
    CP_COMMIT();
}

__global__ __launch_bounds__(256, 2) void k2_gemm_mma(
    float* __restrict__ out, int rowOffset)
{
    extern __shared__ __align__(16) char smem[];
    const uint32_t s0 = smem_u32(smem);

    const int tid  = threadIdx.x;
    const int lane = tid & 31, warp = tid >> 5;
    const int warp_m = warp & 3;
    const int warp_n = warp >> 2;
    const size_t rowBase = (size_t)rowOffset + (size_t)blockIdx.x * 128;

    float acc[2][8][4];
    #pragma unroll
    for (int mt = 0; mt < 2; mt++)
        #pragma unroll
        for (int nt = 0; nt < 8; nt++)
            #pragma unroll
            for (int e = 0; e < 4; e++) acc[mt][nt][e] = 0.0f;

    // prologue: chunk 0 -> stage 0
    k2_load_chunk(s0, rowBase, 0, tid);

    for (int t = 0; t < RDIM / 32; t++) {
        if (t + 1 < RDIM / 32)
            k2_load_chunk(s0 + ((t + 1) & 1) * STAGE_BYTES, rowBase,
                          (t + 1) * 32, tid);
        if (t + 1 < RDIM / 32) { CP_WAIT(1); } else { CP_WAIT(0); }
        __syncthreads();

        const uint32_t stg = s0 + (t & 1) * STAGE_BYTES;
        const uint32_t aAh = stg, aAl = stg + OFF_AL;
        const uint32_t aBh = stg + OFF_BH, aBl = stg + OFF_BL;

        #pragma unroll
        for (int ks = 0; ks < 32; ks += 16) {
            uint32_t Afh[2][4], Afl[2][4];
            #pragma unroll
            for (int mt = 0; mt < 2; mt++) {
                const int r = warp_m * 32 + mt * 16 + (lane & 15);
                const int col = ks + ((lane >> 4) << 3);
                const uint32_t off = (uint32_t)(r * SA + col) * 2;
                ldmatrix_x4(Afh[mt], aAh + off);
                ldmatrix_x4(Afl[mt], aAl + off);
            }
            #pragma unroll
            for (int g = 0; g < 4; g++) {
                uint32_t Bfh[4], Bfl[4];
                const int kr = ks + (lane & 15);
                const int nc = warp_n * 64 + g * 16 + ((lane >> 4) << 3);
                const uint32_t off = (uint32_t)(kr * SB + nc) * 2;
                ldmatrix_x4_t(Bfh, aBh + off);
                ldmatrix_x4_t(Bfl, aBl + off);
                #pragma unroll
                for (int mt = 0; mt < 2; mt++) {
                    mma16816(acc[mt][2 * g],     Afh[mt], &Bfh[0]);
                    mma16816(acc[mt][2 * g + 1], Afh[mt], &Bfh[2]);
                    mma16816(acc[mt][2 * g],     Afh[mt], &Bfl[0]);
                    mma16816(acc[mt][2 * g + 1], Afh[mt], &Bfl[2]);
                    mma16816(acc[mt][2 * g],     Afl[mt], &Bfh[0]);
                    mma16816(acc[mt][2 * g + 1], Afl[mt], &Bfh[2]);
                }
            }
        }
        __syncthreads();
    }

    #pragma unroll
    for (int mt = 0; mt < 2; mt++) {
        const int r0 = (int)rowBase + warp_m * 32 + mt * 16 + (lane >> 2);
        #pragma unroll
        for (int nt = 0; nt < 8; nt++) {
            const int c0 = warp_n * 64 + nt * 8 + (lane & 3) * 2;
            *reinterpret_cast<float2*>(out + (size_t)r0 * OUT_F + c0) =
                make_float2(acc[mt][nt][0], acc[mt][nt][1]);
            *reinterpret_cast<float2*>(out + (size_t)(r0 + 8) * OUT_F + c0) =
                make_float2(acc[mt][nt][2], acc[mt][nt][3]);
        }
    }
}

// =====================================================================
// K3a / K3b / K4
// =====================================================================
__global__ __launch_bounds__(256) void k3a_partial(const float* __restrict__ x)
{
    const int t = threadIdx.x;
    const int c = t & 127, h = t >> 7;
    float s = 0.0f, q = 0.0f;
    const size_t rowBase = (size_t)blockIdx.x * 256;
    for (int r = 0; r < 128; r++) {
        const float v = x[(rowBase + (size_t)r * 2 + h) * OUT_F + c];
        s += v;
        q = fmaf(v, v, q);
    }
    __shared__ float ss[256], sq[256];
    ss[t] = s; sq[t] = q;
    __syncthreads();
    if (t < 128) {
        g_psum[blockIdx.x * OUT_F + t] = ss[t] + ss[t + 128];
        g_psq [blockIdx.x * OUT_F + t] = sq[t] + sq[t + 128];
    }
}

__global__ __launch_bounds__(256) void k3b_finalize(const float* __restrict__ gamma,
                                                    const float* __restrict__ beta)
{
    __shared__ float ss[256], qq[256];
    const int c = blockIdx.x;
    const int t = threadIdx.x;
    ss[t] = g_psum[t * OUT_F + c];
    qq[t] = g_psq [t * OUT_F + c];
    __syncthreads();
    #pragma unroll
    for (int stp = 128; stp > 0; stp >>= 1) {
        if (t < stp) { ss[t] += ss[t + stp]; qq[t] += qq[t + stp]; }
        __syncthreads();
    }
    if (t == 0) {
        const float inv_n = 1.0f / (float)N_PTS;
        const float mean = ss[0] * inv_n;
        const float var  = qq[0] * inv_n - mean * mean;
        const float sc   = gamma[c] * rsqrtf(var + BN_EPS);
        g_scale[c] = sc;
        g_bias[c]  = beta[c] - mean * sc;
    }
}

__global__ __launch_bounds__(256) void k4_bnrelu(float* __restrict__ x)
{
    const int i = blockIdx.x * 256 + threadIdx.x;
    float4 v = reinterpret_cast<float4*>(x)[i];
    const int c0 = (i * 4) & 127;
    const float4 sc = *reinterpret_cast<const float4*>(g_scale + c0);
    const float4 bi = *reinterpret_cast<const float4*>(g_bias + c0);
    v.x = fmaf(v.x, sc.x, bi.x); v.x = (v.x >= 0.0f) ? v.x : NEG_SLOPE * v.x;
    v.y = fmaf(v.y, sc.y, bi.y); v.y = (v.y >= 0.0f) ? v.y : NEG_SLOPE * v.y;
    v.z = fmaf(v.z, sc.z, bi.z); v.z = (v.z >= 0.0f) ? v.z : NEG_SLOPE * v.z;
    v.w = fmaf(v.w, sc.w, bi.w); v.w = (v.w >= 0.0f) ? v.w : NEG_SLOPE * v.w;
    reinterpret_cast<float4*>(x)[i] = v;
}

// =====================================================================
extern "C" void kernel_launch(void* const* d_in, const int* in_sizes, int n_in,
                              void* d_out, int out_size)
{
    const float* qp    = (const float*)d_in[0];
    const float* sp    = (const float*)d_in[1];
    const int*   nbr   = (const int*)  d_in[2];
    const float* feat  = (const float*)d_in[3];
    const float* kpts  = (const float*)d_in[4];
    const float* Wf    = (const float*)d_in[5];
    const float* gamma = (const float*)d_in[6];
    const float* beta  = (const float*)d_in[7];
    float* out = (float*)d_out;

    cudaFuncSetAttribute(k2_gemm_mma,
                         cudaFuncAttributeMaxDynamicSharedMemorySize, K2_SMEM);

    k0_prep<<<(RDIM * OUT_F + 255) / 256, 256>>>(Wf);
    for (int s = 0; s < N_SLICES; s++) {
        const int off = s * SLICE_PTS;
        k1_weighted<<<SLICE_PTS / 16, 256>>>(qp, sp, nbr, feat, kpts, off);
        k2_gemm_mma<<<SLICE_PTS / 128, 256, K2_SMEM>>>(out, off);
    }
    k3a_partial<<<256, 256>>>(out);
    k3b_finalize<<<OUT_F, 256>>>(gamma, beta);
    k4_bnrelu<<<(N_PTS * OUT_F / 4) / 256, 256>>>(out);
}

// round 7
// speedup vs baseline: 1.1939x; 1.1939x over previous
#include <cuda_runtime.h>
#include <cuda_fp16.h>
#include <math.h>
#include <stdint.h>

typedef unsigned long long ull;

// Problem constants
constexpr int N_PTS   = 65536;
constexpr int KP      = 15;
constexpr int IN_F    = 64;
constexpr int OUT_F   = 128;
constexpr int RDIM    = KP * IN_F;          // 960
constexpr float INV_EXT = 1.0f / 0.024f;
constexpr float BN_EPS  = 1e-6f;
constexpr float NEG_SLOPE = 0.1f;

// Scratch
__device__ __half g_Ph[(size_t)N_PTS * RDIM];
__device__ __half g_Pl[(size_t)N_PTS * RDIM];
__device__ __half g_Whh[(size_t)RDIM * OUT_F];
__device__ __half g_Whl[(size_t)RDIM * OUT_F];
__device__ float g_psum[256 * OUT_F];
__device__ float g_psq [256 * OUT_F];
__device__ float g_scale[OUT_F];
__device__ float g_bias [OUT_F];

// ---- packed f32x2 helpers ----
__device__ __forceinline__ ull pk2(float lo, float hi) {
    ull r; asm("mov.b64 %0, {%1, %2};" : "=l"(r) : "f"(lo), "f"(hi)); return r;
}
__device__ __forceinline__ void up2(ull v, float& lo, float& hi) {
    asm("mov.b64 {%0, %1}, %2;" : "=f"(lo), "=f"(hi) : "l"(v));
}
__device__ __forceinline__ ull fma2(ull a, ull b, ull c) {
    ull d; asm("fma.rn.f32x2 %0, %1, %2, %3;" : "=l"(d) : "l"(a), "l"(b), "l"(c));
    return d;
}

__device__ __forceinline__ uint32_t smem_u32(const void* p) {
    uint32_t a;
    asm("{ .reg .u64 t; cvta.to.shared.u64 t, %1; cvt.u32.u64 %0, t; }" : "=r"(a) : "l"(p));
    return a;
}

// ---- mma.sync helpers ----
__device__ __forceinline__ void ldmatrix_x4(uint32_t* r, uint32_t addr) {
    asm volatile("ldmatrix.sync.aligned.m8n8.x4.shared.b16 {%0,%1,%2,%3}, [%4];"
                 : "=r"(r[0]), "=r"(r[1]), "=r"(r[2]), "=r"(r[3]) : "r"(addr));
}
__device__ __forceinline__ void ldmatrix_x4_t(uint32_t* r, uint32_t addr) {
    asm volatile("ldmatrix.sync.aligned.m8n8.x4.trans.shared.b16 {%0,%1,%2,%3}, [%4];"
                 : "=r"(r[0]), "=r"(r[1]), "=r"(r[2]), "=r"(r[3]) : "r"(addr));
}
__device__ __forceinline__ void mma16816(float* c, const uint32_t* a,
                                         const uint32_t* b) {
    asm volatile(
        "mma.sync.aligned.m16n8k16.row.col.f32.f16.f16.f32 "
        "{%0,%1,%2,%3}, {%4,%5,%6,%7}, {%8,%9}, {%0,%1,%2,%3};"
        : "+f"(c[0]), "+f"(c[1]), "+f"(c[2]), "+f"(c[3])
        : "r"(a[0]), "r"(a[1]), "r"(a[2]), "r"(a[3]), "r"(b[0]), "r"(b[1]));
}

// =====================================================================
// K0: split W[k][o] -> fp16 hi/lo
// =====================================================================
__global__ __launch_bounds__(256) void k0_prep(const float* __restrict__ W) {
    const int idx = blockIdx.x * 256 + threadIdx.x;
    if (idx >= RDIM * OUT_F) return;
    const float w = W[idx];
    const __half hi = __float2half_rn(w);
    g_Whh[idx] = hi;
    g_Whl[idx] = __float2half_rn(w - __half2float(hi));
}

// =====================================================================
// K1 v2: one warp per point. 32 lanes x 2 features.
// acc regs: 15 ull (vs 30), weights packed f32x2 in smem [k][m].
// =====================================================================
__global__ __launch_bounds__(256, 4) void k1_weighted(
    const float* __restrict__ qp, const float* __restrict__ sp,
    const int*   __restrict__ nbr, const float* __restrict__ feat,
    const float* __restrict__ kpts)
{
    __shared__ float kp_s[KP][3];
    __shared__ ull   w2_s[8][16][32];   // [warp][k][m] packed (w,w); 32KB

    const int t = threadIdx.x;
    const int warp = t >> 5, lane = t & 31;
    const int gpt = blockIdx.x * 8 + warp;

    if (t < 45) ((float*)kp_s)[t] = kpts[t];
    __syncthreads();

    // lane m owns neighbor m
    const int j = __ldg(nbr + (size_t)gpt * 32 + lane);
    const float qx = __ldg(qp + gpt * 3 + 0);
    const float qy = __ldg(qp + gpt * 3 + 1);
    const float qz = __ldg(qp + gpt * 3 + 2);
    const float dx = __ldg(sp + (size_t)j * 3 + 0) - qx;
    const float dy = __ldg(sp + (size_t)j * 3 + 1) - qy;
    const float dz = __ldg(sp + (size_t)j * 3 + 2) - qz;

    #pragma unroll
    for (int k = 0; k < KP; k++) {
        const float ax = dx - kp_s[k][0];
        const float ay = dy - kp_s[k][1];
        const float az = dz - kp_s[k][2];
        const float sq = ax * ax + ay * ay + az * az;
        const float w = fmaxf(1.0f - sqrtf(sq) * INV_EXT, 0.0f);
        w2_s[warp][k][lane] = pk2(w, w);   // conflict-free: lane-consecutive
    }
    __syncwarp();

    // accumulate: lane owns features [2*lane, 2*lane+1]
    ull acc[KP];
    #pragma unroll
    for (int k = 0; k < KP; k++) acc[k] = 0ull;

    #pragma unroll 4
    for (int m = 0; m < 32; m++) {
        const int jj = __shfl_sync(0xffffffffu, j, m);
        const float2 f = __ldg(reinterpret_cast<const float2*>(
            feat + (size_t)jj * IN_F) + lane);
        const ull fp = pk2(f.x, f.y);
        #pragma unroll
        for (int k = 0; k < KP; k++)
            acc[k] = fma2(w2_s[warp][k][m], fp, acc[k]);   // broadcast LDS.64
    }

    // epilogue: fp16 hi/lo split, coalesced half2 stores
    const size_t rbase = (size_t)gpt * RDIM + lane * 2;
    #pragma unroll
    for (int k = 0; k < KP; k++) {
        float vx, vy;
        up2(acc[k], vx, vy);
        const __half hx = __float2half_rn(vx), hy = __float2half_rn(vy);
        const __half lx = __float2half_rn(vx - __half2float(hx));
        const __half ly = __float2half_rn(vy - __half2float(hy));
        *reinterpret_cast<__half2*>(g_Ph + rbase + k * IN_F) = __halves2half2(hx, hy);
        *reinterpret_cast<__half2*>(g_Pl + rbase + k * IN_F) = __halves2half2(lx, ly);
    }
}

// =====================================================================
// K2: R5 version (reg-prefetch, unsliced) — best-known config
// =====================================================================
constexpr int SA = 40;
constexpr int SB = 136;

__global__ __launch_bounds__(256) void k2_gemm_mma(float* __restrict__ out)
{
    __shared__ __half sAh[128 * SA], sAl[128 * SA];
    __shared__ __half sBh[32 * SB],  sBl[32 * SB];

    const int tid  = threadIdx.x;
    const int lane = tid & 31, warp = tid >> 5;
    const int warp_m = warp & 3;
    const int warp_n = warp >> 2;
    const size_t rowBase = (size_t)blockIdx.x * 128;

    float acc[2][8][4];
    #pragma unroll
    for (int mt = 0; mt < 2; mt++)
        #pragma unroll
        for (int nt = 0; nt < 8; nt++)
            #pragma unroll
            for (int e = 0; e < 4; e++) acc[mt][nt][e] = 0.0f;

    uint4 pah[2], pal[2], pbh[2], pbl[2];
    {
        #pragma unroll
        for (int p = 0; p < 2; p++) {
            const int idx = p * 256 + tid;
            const int row = idx >> 2, c = idx & 3;
            const size_t go = (rowBase + row) * RDIM + c * 8;
            pah[p] = *reinterpret_cast<const uint4*>(g_Ph + go);
            pal[p] = *reinterpret_cast<const uint4*>(g_Pl + go);
            const int brow = idx >> 4, bc = idx & 15;
            const size_t gb = (size_t)brow * OUT_F + bc * 8;
            pbh[p] = *reinterpret_cast<const uint4*>(g_Whh + gb);
            pbl[p] = *reinterpret_cast<const uint4*>(g_Whl + gb);
        }
    }

    const uint32_t aAh = smem_u32(sAh), aAl = smem_u32(sAl);
    const uint32_t aBh = smem_u32(sBh), aBl = smem_u32(sBl);

    for (int t = 0; t < RDIM / 32; t++) {
        #pragma unroll
        for (int p = 0; p < 2; p++) {
            const int idx = p * 256 + tid;
            const int row = idx >> 2, c = idx & 3;
            *reinterpret_cast<uint4*>(sAh + row * SA + c * 8) = pah[p];
            *reinterpret_cast<uint4*>(sAl + row * SA + c * 8) = pal[p];
            const int brow = idx >> 4, bc = idx & 15;
            *reinterpret_cast<uint4*>(sBh + brow * SB + bc * 8) = pbh[p];
            *reinterpret_cast<uint4*>(sBl + brow * SB + bc * 8) = pbl[p];
        }
        __syncthreads();

        if (t < RDIM / 32 - 1) {
            const int kn = (t + 1) * 32;
            #pragma unroll
            for (int p = 0; p < 2; p++) {
                const int idx = p * 256 + tid;
                const int row = idx >> 2, c = idx & 3;
                const size_t go = (rowBase + row) * RDIM + kn + c * 8;
                pah[p] = *reinterpret_cast<const uint4*>(g_Ph + go);
                pal[p] = *reinterpret_cast<const uint4*>(g_Pl + go);
                const int brow = idx >> 4, bc = idx & 15;
                const size_t gb = (size_t)(kn + brow) * OUT_F + bc * 8;
                pbh[p] = *reinterpret_cast<const uint4*>(g_Whh + gb);
                pbl[p] = *reinterpret_cast<const uint4*>(g_Whl + gb);
            }
        }

        #pragma unroll
        for (int ks = 0; ks < 32; ks += 16) {
            uint32_t Afh[2][4], Afl[2][4];
            #pragma unroll
            for (int mt = 0; mt < 2; mt++) {
                const int r = warp_m * 32 + mt * 16 + (lane & 15);
                const int col = ks + ((lane >> 4) << 3);
                const uint32_t off = (uint32_t)(r * SA + col) * 2;
                ldmatrix_x4(Afh[mt], aAh + off);
                ldmatrix_x4(Afl[mt], aAl + off);
            }
            #pragma unroll
            for (int g = 0; g < 4; g++) {
                uint32_t Bfh[4], Bfl[4];
                const int kr = ks + (lane & 15);
                const int nc = warp_n * 64 + g * 16 + ((lane >> 4) << 3);
                const uint32_t off = (uint32_t)(kr * SB + nc) * 2;
                ldmatrix_x4_t(Bfh, aBh + off);
                ldmatrix_x4_t(Bfl, aBl + off);
                #pragma unroll
                for (int mt = 0; mt < 2; mt++) {
                    mma16816(acc[mt][2 * g],     Afh[mt], &Bfh[0]);
                    mma16816(acc[mt][2 * g + 1], Afh[mt], &Bfh[2]);
                    mma16816(acc[mt][2 * g],     Afh[mt], &Bfl[0]);
                    mma16816(acc[mt][2 * g + 1], Afh[mt], &Bfl[2]);
                    mma16816(acc[mt][2 * g],     Afl[mt], &Bfh[0]);
                    mma16816(acc[mt][2 * g + 1], Afl[mt], &Bfh[2]);
                }
            }
        }
        __syncthreads();
    }

    #pragma unroll
    for (int mt = 0; mt < 2; mt++) {
        const int r0 = (int)rowBase + warp_m * 32 + mt * 16 + (lane >> 2);
        #pragma unroll
        for (int nt = 0; nt < 8; nt++) {
            const int c0 = warp_n * 64 + nt * 8 + (lane & 3) * 2;
            *reinterpret_cast<float2*>(out + (size_t)r0 * OUT_F + c0) =
                make_float2(acc[mt][nt][0], acc[mt][nt][1]);
            *reinterpret_cast<float2*>(out + (size_t)(r0 + 8) * OUT_F + c0) =
                make_float2(acc[mt][nt][2], acc[mt][nt][3]);
        }
    }
}

// =====================================================================
// K3a / K3b / K4
// =====================================================================
__global__ __launch_bounds__(256) void k3a_partial(const float* __restrict__ x)
{
    const int t = threadIdx.x;
    const int c = t & 127, h = t >> 7;
    float s = 0.0f, q = 0.0f;
    const size_t rowBase = (size_t)blockIdx.x * 256;
    for (int r = 0; r < 128; r++) {
        const float v = x[(rowBase + (size_t)r * 2 + h) * OUT_F + c];
        s += v;
        q = fmaf(v, v, q);
    }
    __shared__ float ss[256], sq[256];
    ss[t] = s; sq[t] = q;
    __syncthreads();
    if (t < 128) {
        g_psum[blockIdx.x * OUT_F + t] = ss[t] + ss[t + 128];
        g_psq [blockIdx.x * OUT_F + t] = sq[t] + sq[t + 128];
    }
}

__global__ __launch_bounds__(256) void k3b_finalize(const float* __restrict__ gamma,
                                                    const float* __restrict__ beta)
{
    __shared__ float ss[256], qq[256];
    const int c = blockIdx.x;
    const int t = threadIdx.x;
    ss[t] = g_psum[t * OUT_F + c];
    qq[t] = g_psq [t * OUT_F + c];
    __syncthreads();
    #pragma unroll
    for (int stp = 128; stp > 0; stp >>= 1) {
        if (t < stp) { ss[t] += ss[t + stp]; qq[t] += qq[t + stp]; }
        __syncthreads();
    }
    if (t == 0) {
        const float inv_n = 1.0f / (float)N_PTS;
        const float mean = ss[0] * inv_n;
        const float var  = qq[0] * inv_n - mean * mean;
        const float sc   = gamma[c] * rsqrtf(var + BN_EPS);
        g_scale[c] = sc;
        g_bias[c]  = beta[c] - mean * sc;
    }
}

__global__ __launch_bounds__(256) void k4_bnrelu(float* __restrict__ x)
{
    const int i = blockIdx.x * 256 + threadIdx.x;
    float4 v = reinterpret_cast<float4*>(x)[i];
    const int c0 = (i * 4) & 127;
    const float4 sc = *reinterpret_cast<const float4*>(g_scale + c0);
    const float4 bi = *reinterpret_cast<const float4*>(g_bias + c0);
    v.x = fmaf(v.x, sc.x, bi.x); v.x = (v.x >= 0.0f) ? v.x : NEG_SLOPE * v.x;
    v.y = fmaf(v.y, sc.y, bi.y); v.y = (v.y >= 0.0f) ? v.y : NEG_SLOPE * v.y;
    v.z = fmaf(v.z, sc.z, bi.z); v.z = (v.z >= 0.0f) ? v.z : NEG_SLOPE * v.z;
    v.w = fmaf(v.w, sc.w, bi.w); v.w = (v.w >= 0.0f) ? v.w : NEG_SLOPE * v.w;
    reinterpret_cast<float4*>(x)[i] = v;
}

// =====================================================================
extern "C" void kernel_launch(void* const* d_in, const int* in_sizes, int n_in,
                              void* d_out, int out_size)
{
    const float* qp    = (const float*)d_in[0];
    const float* sp    = (const float*)d_in[1];
    const int*   nbr   = (const int*)  d_in[2];
    const float* feat  = (const float*)d_in[3];
    const float* kpts  = (const float*)d_in[4];
    const float* Wf    = (const float*)d_in[5];
    const float* gamma = (const float*)d_in[6];
    const float* beta  = (const float*)d_in[7];
    float* out = (float*)d_out;

    k0_prep<<<(RDIM * OUT_F + 255) / 256, 256>>>(Wf);
    k1_weighted<<<N_PTS / 8, 256>>>(qp, sp, nbr, feat, kpts);
    k2_gemm_mma<<<N_PTS / 128, 256>>>(out);
    k3a_partial<<<256, 256>>>(out);
    k3b_finalize<<<OUT_F, 256>>>(gamma, beta);
    k4_bnrelu<<<(N_PTS * OUT_F / 4) / 256, 256>>>(out);
}

// round 8
// speedup vs baseline: 1.2016x; 1.0065x over previous
#include <cuda_runtime.h>
#include <cuda_fp16.h>
#include <math.h>
#include <stdint.h>

typedef unsigned long long ull;

// Problem constants
constexpr int N_PTS   = 65536;
constexpr int KP      = 15;
constexpr int IN_F    = 64;
constexpr int OUT_F   = 128;
constexpr int RDIM    = KP * IN_F;          // 960
constexpr float INV_EXT = 1.0f / 0.024f;
constexpr float BN_EPS  = 1e-6f;
constexpr float NEG_SLOPE = 0.1f;

// Scratch
__device__ __half g_Ph[(size_t)N_PTS * RDIM];
__device__ __half g_Pl[(size_t)N_PTS * RDIM];
__device__ __half g_Whh[(size_t)RDIM * OUT_F];
__device__ __half g_Whl[(size_t)RDIM * OUT_F];
__device__ float g_psum[256 * OUT_F];
__device__ float g_psq [256 * OUT_F];
__device__ float g_scale[OUT_F];
__device__ float g_bias [OUT_F];

// ---- packed f32x2 helpers ----
__device__ __forceinline__ ull pk2(float lo, float hi) {
    ull r; asm("mov.b64 %0, {%1, %2};" : "=l"(r) : "f"(lo), "f"(hi)); return r;
}
__device__ __forceinline__ void up2(ull v, float& lo, float& hi) {
    asm("mov.b64 {%0, %1}, %2;" : "=f"(lo), "=f"(hi) : "l"(v));
}
__device__ __forceinline__ ull fma2(ull a, ull b, ull c) {
    ull d; asm("fma.rn.f32x2 %0, %1, %2, %3;" : "=l"(d) : "l"(a), "l"(b), "l"(c));
    return d;
}

__device__ __forceinline__ uint32_t smem_u32(const void* p) {
    uint32_t a;
    asm("{ .reg .u64 t; cvta.to.shared.u64 t, %1; cvt.u32.u64 %0, t; }" : "=r"(a) : "l"(p));
    return a;
}

// ---- mma.sync helpers ----
__device__ __forceinline__ void ldmatrix_x4(uint32_t* r, uint32_t addr) {
    asm volatile("ldmatrix.sync.aligned.m8n8.x4.shared.b16 {%0,%1,%2,%3}, [%4];"
                 : "=r"(r[0]), "=r"(r[1]), "=r"(r[2]), "=r"(r[3]) : "r"(addr));
}
__device__ __forceinline__ void ldmatrix_x4_t(uint32_t* r, uint32_t addr) {
    asm volatile("ldmatrix.sync.aligned.m8n8.x4.trans.shared.b16 {%0,%1,%2,%3}, [%4];"
                 : "=r"(r[0]), "=r"(r[1]), "=r"(r[2]), "=r"(r[3]) : "r"(addr));
}
__device__ __forceinline__ void mma16816(float* c, const uint32_t* a,
                                         const uint32_t* b) {
    asm volatile(
        "mma.sync.aligned.m16n8k16.row.col.f32.f16.f16.f32 "
        "{%0,%1,%2,%3}, {%4,%5,%6,%7}, {%8,%9}, {%0,%1,%2,%3};"
        : "+f"(c[0]), "+f"(c[1]), "+f"(c[2]), "+f"(c[3])
        : "r"(a[0]), "r"(a[1]), "r"(a[2]), "r"(a[3]), "r"(b[0]), "r"(b[1]));
}

// =====================================================================
// K0: split W[k][o] -> fp16 hi/lo
// =====================================================================
__global__ __launch_bounds__(256) void k0_prep(const float* __restrict__ W) {
    const int idx = blockIdx.x * 256 + threadIdx.x;
    if (idx >= RDIM * OUT_F) return;
    const float w = W[idx];
    const __half hi = __float2half_rn(w);
    g_Whh[idx] = hi;
    g_Whl[idx] = __float2half_rn(w - __half2float(hi));
}

// =====================================================================
// K1 v2: one warp per point. 32 lanes x 2 features.
// acc regs: 15 ull (vs 30), weights packed f32x2 in smem [k][m].
// =====================================================================
__global__ __launch_bounds__(256, 4) void k1_weighted(
    const float* __restrict__ qp, const float* __restrict__ sp,
    const int*   __restrict__ nbr, const float* __restrict__ feat,
    const float* __restrict__ kpts)
{
    __shared__ float kp_s[KP][3];
    __shared__ ull   w2_s[8][16][32];   // [warp][k][m] packed (w,w); 32KB

    const int t = threadIdx.x;
    const int warp = t >> 5, lane = t & 31;
    const int gpt = blockIdx.x * 8 + warp;

    if (t < 45) ((float*)kp_s)[t] = kpts[t];
    __syncthreads();

    // lane m owns neighbor m
    const int j = __ldg(nbr + (size_t)gpt * 32 + lane);
    const float qx = __ldg(qp + gpt * 3 + 0);
    const float qy = __ldg(qp + gpt * 3 + 1);
    const float qz = __ldg(qp + gpt * 3 + 2);
    const float dx = __ldg(sp + (size_t)j * 3 + 0) - qx;
    const float dy = __ldg(sp + (size_t)j * 3 + 1) - qy;
    const float dz = __ldg(sp + (size_t)j * 3 + 2) - qz;

    #pragma unroll
    for (int k = 0; k < KP; k++) {
        const float ax = dx - kp_s[k][0];
        const float ay = dy - kp_s[k][1];
        const float az = dz - kp_s[k][2];
        const float sq = ax * ax + ay * ay + az * az;
        const float w = fmaxf(1.0f - sqrtf(sq) * INV_EXT, 0.0f);
        w2_s[warp][k][lane] = pk2(w, w);   // conflict-free: lane-consecutive
    }
    __syncwarp();

    // accumulate: lane owns features [2*lane, 2*lane+1]
    ull acc[KP];
    #pragma unroll
    for (int k = 0; k < KP; k++) acc[k] = 0ull;

    #pragma unroll 4
    for (int m = 0; m < 32; m++) {
        const int jj = __shfl_sync(0xffffffffu, j, m);
        const float2 f = __ldg(reinterpret_cast<const float2*>(
            feat + (size_t)jj * IN_F) + lane);
        const ull fp = pk2(f.x, f.y);
        #pragma unroll
        for (int k = 0; k < KP; k++)
            acc[k] = fma2(w2_s[warp][k][m], fp, acc[k]);   // broadcast LDS.64
    }

    // epilogue: fp16 hi/lo split, coalesced half2 stores
    const size_t rbase = (size_t)gpt * RDIM + lane * 2;
    #pragma unroll
    for (int k = 0; k < KP; k++) {
        float vx, vy;
        up2(acc[k], vx, vy);
        const __half hx = __float2half_rn(vx), hy = __float2half_rn(vy);
        const __half lx = __float2half_rn(vx - __half2float(hx));
        const __half ly = __float2half_rn(vy - __half2float(hy));
        *reinterpret_cast<__half2*>(g_Ph + rbase + k * IN_F) = __halves2half2(hx, hy);
        *reinterpret_cast<__half2*>(g_Pl + rbase + k * IN_F) = __halves2half2(lx, ly);
    }
}

// =====================================================================
// K2: R5 version (reg-prefetch, unsliced) — best-known config
// =====================================================================
constexpr int SA = 40;
constexpr int SB = 136;

__global__ __launch_bounds__(256) void k2_gemm_mma(float* __restrict__ out)
{
    __shared__ __half sAh[128 * SA], sAl[128 * SA];
    __shared__ __half sBh[32 * SB],  sBl[32 * SB];

    const int tid  = threadIdx.x;
    const int lane = tid & 31, warp = tid >> 5;
    const int warp_m = warp & 3;
    const int warp_n = warp >> 2;
    const size_t rowBase = (size_t)blockIdx.x * 128;

    float acc[2][8][4];
    #pragma unroll
    for (int mt = 0; mt < 2; mt++)
        #pragma unroll
        for (int nt = 0; nt < 8; nt++)
            #pragma unroll
            for (int e = 0; e < 4; e++) acc[mt][nt][e] = 0.0f;

    uint4 pah[2], pal[2], pbh[2], pbl[2];
    {
        #pragma unroll
        for (int p = 0; p < 2; p++) {
            const int idx = p * 256 + tid;
            const int row = idx >> 2, c = idx & 3;
            const size_t go = (rowBase + row) * RDIM + c * 8;
            pah[p] = *reinterpret_cast<const uint4*>(g_Ph + go);
            pal[p] = *reinterpret_cast<const uint4*>(g_Pl + go);
            const int brow = idx >> 4, bc = idx & 15;
            const size_t gb = (size_t)brow * OUT_F + bc * 8;
            pbh[p] = *reinterpret_cast<const uint4*>(g_Whh + gb);
            pbl[p] = *reinterpret_cast<const uint4*>(g_Whl + gb);
        }
    }

    const uint32_t aAh = smem_u32(sAh), aAl = smem_u32(sAl);
    const uint32_t aBh = smem_u32(sBh), aBl = smem_u32(sBl);

    for (int t = 0; t < RDIM / 32; t++) {
        #pragma unroll
        for (int p = 0; p < 2; p++) {
            const int idx = p * 256 + tid;
            const int row = idx >> 2, c = idx & 3;
            *reinterpret_cast<uint4*>(sAh + row * SA + c * 8) = pah[p];
            *reinterpret_cast<uint4*>(sAl + row * SA + c * 8) = pal[p];
            const int brow = idx >> 4, bc = idx & 15;
            *reinterpret_cast<uint4*>(sBh + brow * SB + bc * 8) = pbh[p];
            *reinterpret_cast<uint4*>(sBl + brow * SB + bc * 8) = pbl[p];
        }
        __syncthreads();

        if (t < RDIM / 32 - 1) {
            const int kn = (t + 1) * 32;
            #pragma unroll
            for (int p = 0; p < 2; p++) {
                const int idx = p * 256 + tid;
                const int row = idx >> 2, c = idx & 3;
                const size_t go = (rowBase + row) * RDIM + kn + c * 8;
                pah[p] = *reinterpret_cast<const uint4*>(g_Ph + go);
                pal[p] = *reinterpret_cast<const uint4*>(g_Pl + go);
                const int brow = idx >> 4, bc = idx & 15;
                const size_t gb = (size_t)(kn + brow) * OUT_F + bc * 8;
                pbh[p] = *reinterpret_cast<const uint4*>(g_Whh + gb);
                pbl[p] = *reinterpret_cast<const uint4*>(g_Whl + gb);
            }
        }

        #pragma unroll
        for (int ks = 0; ks < 32; ks += 16) {
            uint32_t Afh[2][4], Afl[2][4];
            #pragma unroll
            for (int mt = 0; mt < 2; mt++) {
                const int r = warp_m * 32 + mt * 16 + (lane & 15);
                const int col = ks + ((lane >> 4) << 3);
                const uint32_t off = (uint32_t)(r * SA + col) * 2;
                ldmatrix_x4(Afh[mt], aAh + off);
                ldmatrix_x4(Afl[mt], aAl + off);
            }
            #pragma unroll
            for (int g = 0; g < 4; g++) {
                uint32_t Bfh[4], Bfl[4];
                const int kr = ks + (lane & 15);
                const int nc = warp_n * 64 + g * 16 + ((lane >> 4) << 3);
                const uint32_t off = (uint32_t)(kr * SB + nc) * 2;
                ldmatrix_x4_t(Bfh, aBh + off);
                ldmatrix_x4_t(Bfl, aBl + off);
                #pragma unroll
                for (int mt = 0; mt < 2; mt++) {
                    mma16816(acc[mt][2 * g],     Afh[mt], &Bfh[0]);
                    mma16816(acc[mt][2 * g + 1], Afh[mt], &Bfh[2]);
                    mma16816(acc[mt][2 * g],     Afh[mt], &Bfl[0]);
                    mma16816(acc[mt][2 * g + 1], Afh[mt], &Bfl[2]);
                    mma16816(acc[mt][2 * g],     Afl[mt], &Bfh[0]);
                    mma16816(acc[mt][2 * g + 1], Afl[mt], &Bfh[2]);
                }
            }
        }
        __syncthreads();
    }

    #pragma unroll
    for (int mt = 0; mt < 2; mt++) {
        const int r0 = (int)rowBase + warp_m * 32 + mt * 16 + (lane >> 2);
        #pragma unroll
        for (int nt = 0; nt < 8; nt++) {
            const int c0 = warp_n * 64 + nt * 8 + (lane & 3) * 2;
            *reinterpret_cast<float2*>(out + (size_t)r0 * OUT_F + c0) =
                make_float2(acc[mt][nt][0], acc[mt][nt][1]);
            *reinterpret_cast<float2*>(out + (size_t)(r0 + 8) * OUT_F + c0) =
                make_float2(acc[mt][nt][2], acc[mt][nt][3]);
        }
    }
}

// =====================================================================
// K3a / K3b / K4
// =====================================================================
__global__ __launch_bounds__(256) void k3a_partial(const float* __restrict__ x)
{
    const int t = threadIdx.x;
    const int c = t & 127, h = t >> 7;
    float s = 0.0f, q = 0.0f;
    const size_t rowBase = (size_t)blockIdx.x * 256;
    for (int r = 0; r < 128; r++) {
        const float v = x[(rowBase + (size_t)r * 2 + h) * OUT_F + c];
        s += v;
        q = fmaf(v, v, q);
    }
    __shared__ float ss[256], sq[256];
    ss[t] = s; sq[t] = q;
    __syncthreads();
    if (t < 128) {
        g_psum[blockIdx.x * OUT_F + t] = ss[t] + ss[t + 128];
        g_psq [blockIdx.x * OUT_F + t] = sq[t] + sq[t + 128];
    }
}

__global__ __launch_bounds__(256) void k3b_finalize(const float* __restrict__ gamma,
                                                    const float* __restrict__ beta)
{
    __shared__ float ss[256], qq[256];
    const int c = blockIdx.x;
    const int t = threadIdx.x;
    ss[t] = g_psum[t * OUT_F + c];
    qq[t] = g_psq [t * OUT_F + c];
    __syncthreads();
    #pragma unroll
    for (int stp = 128; stp > 0; stp >>= 1) {
        if (t < stp) { ss[t] += ss[t + stp]; qq[t] += qq[t + stp]; }
        __syncthreads();
    }
    if (t == 0) {
        const float inv_n = 1.0f / (float)N_PTS;
        const float mean = ss[0] * inv_n;
        const float var  = qq[0] * inv_n - mean * mean;
        const float sc   = gamma[c] * rsqrtf(var + BN_EPS);
        g_scale[c] = sc;
        g_bias[c]  = beta[c] - mean * sc;
    }
}

__global__ __launch_bounds__(256) void k4_bnrelu(float* __restrict__ x)
{
    const int i = blockIdx.x * 256 + threadIdx.x;
    float4 v = reinterpret_cast<float4*>(x)[i];
    const int c0 = (i * 4) & 127;
    const float4 sc = *reinterpret_cast<const float4*>(g_scale + c0);
    const float4 bi = *reinterpret_cast<const float4*>(g_bias + c0);
    v.x = fmaf(v.x, sc.x, bi.x); v.x = (v.x >= 0.0f) ? v.x : NEG_SLOPE * v.x;
    v.y = fmaf(v.y, sc.y, bi.y); v.y = (v.y >= 0.0f) ? v.y : NEG_SLOPE * v.y;
    v.z = fmaf(v.z, sc.z, bi.z); v.z = (v.z >= 0.0f) ? v.z : NEG_SLOPE * v.z;
    v.w = fmaf(v.w, sc.w, bi.w); v.w = (v.w >= 0.0f) ? v.w : NEG_SLOPE * v.w;
    reinterpret_cast<float4*>(x)[i] = v;
}

// =====================================================================
extern "C" void kernel_launch(void* const* d_in, const int* in_sizes, int n_in,
                              void* d_out, int out_size)
{
    const float* qp    = (const float*)d_in[0];
    const float* sp    = (const float*)d_in[1];
    const int*   nbr   = (const int*)  d_in[2];
    const float* feat  = (const float*)d_in[3];
    const float* kpts  = (const float*)d_in[4];
    const float* Wf    = (const float*)d_in[5];
    const float* gamma = (const float*)d_in[6];
    const float* beta  = (const float*)d_in[7];
    float* out = (float*)d_out;

    k0_prep<<<(RDIM * OUT_F + 255) / 256, 256>>>(Wf);
    k1_weighted<<<N_PTS / 8, 256>>>(qp, sp, nbr, feat, kpts);
    k2_gemm_mma<<<N_PTS / 128, 256>>>(out);
    k3a_partial<<<256, 256>>>(out);
    k3b_finalize<<<OUT_F, 256>>>(gamma, beta);
    k4_bnrelu<<<(N_PTS * OUT_F / 4) / 256, 256>>>(out);
}

// round 9
// speedup vs baseline: 1.4803x; 1.2320x over previous
#include <cuda_runtime.h>
#include <cuda_fp16.h>
#include <math.h>
#include <stdint.h>

typedef unsigned long long ull;

// Problem constants
constexpr int N_PTS   = 65536;
constexpr int KP      = 15;
constexpr int IN_F    = 64;
constexpr int OUT_F   = 128;
constexpr int RDIM    = KP * IN_F;          // 960
constexpr float INV_EXT = 1.0f / 0.024f;
constexpr float BN_EPS  = 1e-6f;
constexpr float NEG_SLOPE = 0.1f;

// Scratch
__device__ __half g_Ph[(size_t)N_PTS * RDIM];   // P fp16 (hi only)
__device__ __half g_Whh[(size_t)RDIM * OUT_F];  // W fp16 hi
__device__ __half g_Whl[(size_t)RDIM * OUT_F];  // W fp16 lo residual
__device__ float g_psum[256 * OUT_F];
__device__ float g_psq [256 * OUT_F];
__device__ float g_scale[OUT_F];
__device__ float g_bias [OUT_F];

// ---- packed f32x2 helpers ----
__device__ __forceinline__ ull pk2(float lo, float hi) {
    ull r; asm("mov.b64 %0, {%1, %2};" : "=l"(r) : "f"(lo), "f"(hi)); return r;
}
__device__ __forceinline__ void up2(ull v, float& lo, float& hi) {
    asm("mov.b64 {%0, %1}, %2;" : "=f"(lo), "=f"(hi) : "l"(v));
}
__device__ __forceinline__ ull fma2(ull a, ull b, ull c) {
    ull d; asm("fma.rn.f32x2 %0, %1, %2, %3;" : "=l"(d) : "l"(a), "l"(b), "l"(c));
    return d;
}

__device__ __forceinline__ uint32_t smem_u32(const void* p) {
    uint32_t a;
    asm("{ .reg .u64 t; cvta.to.shared.u64 t, %1; cvt.u32.u64 %0, t; }" : "=r"(a) : "l"(p));
    return a;
}

// ---- mma.sync + cp.async helpers ----
__device__ __forceinline__ void ldmatrix_x4(uint32_t* r, uint32_t addr) {
    asm volatile("ldmatrix.sync.aligned.m8n8.x4.shared.b16 {%0,%1,%2,%3}, [%4];"
                 : "=r"(r[0]), "=r"(r[1]), "=r"(r[2]), "=r"(r[3]) : "r"(addr));
}
__device__ __forceinline__ void ldmatrix_x4_t(uint32_t* r, uint32_t addr) {
    asm volatile("ldmatrix.sync.aligned.m8n8.x4.trans.shared.b16 {%0,%1,%2,%3}, [%4];"
                 : "=r"(r[0]), "=r"(r[1]), "=r"(r[2]), "=r"(r[3]) : "r"(addr));
}
__device__ __forceinline__ void mma16816(float* c, const uint32_t* a,
                                         const uint32_t* b) {
    asm volatile(
        "mma.sync.aligned.m16n8k16.row.col.f32.f16.f16.f32 "
        "{%0,%1,%2,%3}, {%4,%5,%6,%7}, {%8,%9}, {%0,%1,%2,%3};"
        : "+f"(c[0]), "+f"(c[1]), "+f"(c[2]), "+f"(c[3])
        : "r"(a[0]), "r"(a[1]), "r"(a[2]), "r"(a[3]), "r"(b[0]), "r"(b[1]));
}
__device__ __forceinline__ void cp16(uint32_t saddr, const void* gptr) {
    asm volatile("cp.async.cg.shared.global [%0], [%1], 16;"
                 :: "r"(saddr), "l"(gptr) : "memory");
}
#define CP_COMMIT() asm volatile("cp.async.commit_group;" ::: "memory")
#define CP_WAIT(n)  asm volatile("cp.async.wait_group %0;" :: "n"(n) : "memory")

// =====================================================================
// K0: split W[k][o] -> fp16 hi/lo
// =====================================================================
__global__ __launch_bounds__(256) void k0_prep(const float* __restrict__ W) {
    const int idx = blockIdx.x * 256 + threadIdx.x;
    if (idx >= RDIM * OUT_F) return;
    const float w = W[idx];
    const __half hi = __float2half_rn(w);
    g_Whh[idx] = hi;
    g_Whl[idx] = __float2half_rn(w - __half2float(hi));
}

// =====================================================================
// K1: one warp per point; fp16-hi output only
// =====================================================================
__global__ __launch_bounds__(256, 4) void k1_weighted(
    const float* __restrict__ qp, const float* __restrict__ sp,
    const int*   __restrict__ nbr, const float* __restrict__ feat,
    const float* __restrict__ kpts)
{
    __shared__ float kp_s[KP][3];
    __shared__ ull   w2_s[8][16][32];   // [warp][k][m] packed (w,w)

    const int t = threadIdx.x;
    const int warp = t >> 5, lane = t & 31;
    const int gpt = blockIdx.x * 8 + warp;

    if (t < 45) ((float*)kp_s)[t] = kpts[t];
    __syncthreads();

    const int j = __ldg(nbr + (size_t)gpt * 32 + lane);
    const float qx = __ldg(qp + gpt * 3 + 0);
    const float qy = __ldg(qp + gpt * 3 + 1);
    const float qz = __ldg(qp + gpt * 3 + 2);
    const float dx = __ldg(sp + (size_t)j * 3 + 0) - qx;
    const float dy = __ldg(sp + (size_t)j * 3 + 1) - qy;
    const float dz = __ldg(sp + (size_t)j * 3 + 2) - qz;

    #pragma unroll
    for (int k = 0; k < KP; k++) {
        const float ax = dx - kp_s[k][0];
        const float ay = dy - kp_s[k][1];
        const float az = dz - kp_s[k][2];
        const float sq = ax * ax + ay * ay + az * az;
        const float w = fmaxf(1.0f - sqrtf(sq) * INV_EXT, 0.0f);
        w2_s[warp][k][lane] = pk2(w, w);
    }
    __syncwarp();

    ull acc[KP];
    #pragma unroll
    for (int k = 0; k < KP; k++) acc[k] = 0ull;

    #pragma unroll 4
    for (int m = 0; m < 32; m++) {
        const int jj = __shfl_sync(0xffffffffu, j, m);
        const float2 f = __ldg(reinterpret_cast<const float2*>(
            feat + (size_t)jj * IN_F) + lane);
        const ull fp = pk2(f.x, f.y);
        #pragma unroll
        for (int k = 0; k < KP; k++)
            acc[k] = fma2(w2_s[warp][k][m], fp, acc[k]);
    }

    const size_t rbase = (size_t)gpt * RDIM + lane * 2;
    #pragma unroll
    for (int k = 0; k < KP; k++) {
        float vx, vy;
        up2(acc[k], vx, vy);
        *reinterpret_cast<__half2*>(g_Ph + rbase + k * IN_F) =
            __halves2half2(__float2half_rn(vx), __float2half_rn(vy));
    }
}

// =====================================================================
// K2 v3: cp.async 2-stage double buffer, 2-term fp16 GEMM, 2 CTAs/SM
// x = Ph @ (Whh + Whl)
// =====================================================================
constexpr int SA = 40;    // A smem stride (halfs)
constexpr int SB = 136;   // B smem stride (halfs)
constexpr int AH_BYTES = 128 * SA * 2;        // 10240
constexpr int BH_BYTES = 32 * SB * 2;         // 8704
constexpr int OFF_BH   = AH_BYTES;            // 10240
constexpr int OFF_BL   = AH_BYTES + BH_BYTES; // 18944
constexpr int STAGE_BYTES = AH_BYTES + 2 * BH_BYTES; // 27648
constexpr int K2_SMEM  = 2 * STAGE_BYTES;     // 55296

__device__ __forceinline__ void k2_load_chunk(
    uint32_t sbase, size_t rowBase, int k0, int tid)
{
    #pragma unroll
    for (int p = 0; p < 2; p++) {
        const int idx = p * 256 + tid;
        // A: 128 rows x 4 16B-cols (32 halfs/row)
        const int row = idx >> 2, c = idx & 3;
        const size_t go = (rowBase + row) * RDIM + k0 + c * 8;
        cp16(sbase + (uint32_t)(row * SA + c * 8) * 2, g_Ph + go);
        // B: 32 rows x 16 16B-cols (hi and lo)
        const int brow = idx >> 4, bc = idx & 15;
        const size_t gb = (size_t)(k0 + brow) * OUT_F + bc * 8;
        const uint32_t sb = (uint32_t)(brow * SB + bc * 8) * 2;
        cp16(sbase + OFF_BH + sb, g_Whh + gb);
        cp16(sbase + OFF_BL + sb, g_Whl + gb);
    }
    CP_COMMIT();
}

__global__ __launch_bounds__(256, 2) void k2_gemm_mma(float* __restrict__ out)
{
    extern __shared__ __align__(16) char smem[];
    const uint32_t s0 = smem_u32(smem);

    const int tid  = threadIdx.x;
    const int lane = tid & 31, warp = tid >> 5;
    const int warp_m = warp & 3;
    const int warp_n = warp >> 2;
    const size_t rowBase = (size_t)blockIdx.x * 128;

    float acc[2][8][4];
    #pragma unroll
    for (int mt = 0; mt < 2; mt++)
        #pragma unroll
        for (int nt = 0; nt < 8; nt++)
            #pragma unroll
            for (int e = 0; e < 4; e++) acc[mt][nt][e] = 0.0f;

    k2_load_chunk(s0, rowBase, 0, tid);

    for (int t = 0; t < RDIM / 32; t++) {
        if (t + 1 < RDIM / 32) {
            k2_load_chunk(s0 + ((t + 1) & 1) * STAGE_BYTES, rowBase,
                          (t + 1) * 32, tid);
            CP_WAIT(1);
        } else {
            CP_WAIT(0);
        }
        __syncthreads();

        const uint32_t stg = s0 + (t & 1) * STAGE_BYTES;
        const uint32_t aAh = stg;
        const uint32_t aBh = stg + OFF_BH, aBl = stg + OFF_BL;

        #pragma unroll
        for (int ks = 0; ks < 32; ks += 16) {
            uint32_t Afh[2][4];
            #pragma unroll
            for (int mt = 0; mt < 2; mt++) {
                const int r = warp_m * 32 + mt * 16 + (lane & 15);
                const int col = ks + ((lane >> 4) << 3);
                ldmatrix_x4(Afh[mt], aAh + (uint32_t)(r * SA + col) * 2);
            }
            #pragma unroll
            for (int g = 0; g < 4; g++) {
                uint32_t Bfh[4], Bfl[4];
                const int kr = ks + (lane & 15);
                const int nc = warp_n * 64 + g * 16 + ((lane >> 4) << 3);
                const uint32_t off = (uint32_t)(kr * SB + nc) * 2;
                ldmatrix_x4_t(Bfh, aBh + off);
                ldmatrix_x4_t(Bfl, aBl + off);
                #pragma unroll
                for (int mt = 0; mt < 2; mt++) {
                    mma16816(acc[mt][2 * g],     Afh[mt], &Bfh[0]);
                    mma16816(acc[mt][2 * g + 1], Afh[mt], &Bfh[2]);
                    mma16816(acc[mt][2 * g],     Afh[mt], &Bfl[0]);
                    mma16816(acc[mt][2 * g + 1], Afh[mt], &Bfl[2]);
                }
            }
        }
        __syncthreads();
    }

    #pragma unroll
    for (int mt = 0; mt < 2; mt++) {
        const int r0 = (int)rowBase + warp_m * 32 + mt * 16 + (lane >> 2);
        #pragma unroll
        for (int nt = 0; nt < 8; nt++) {
            const int c0 = warp_n * 64 + nt * 8 + (lane & 3) * 2;
            *reinterpret_cast<float2*>(out + (size_t)r0 * OUT_F + c0) =
                make_float2(acc[mt][nt][0], acc[mt][nt][1]);
            *reinterpret_cast<float2*>(out + (size_t)(r0 + 8) * OUT_F + c0) =
                make_float2(acc[mt][nt][2], acc[mt][nt][3]);
        }
    }
}

// =====================================================================
// K3a / K3b / K4
// =====================================================================
__global__ __launch_bounds__(256) void k3a_partial(const float* __restrict__ x)
{
    const int t = threadIdx.x;
    const int c = t & 127, h = t >> 7;
    float s = 0.0f, q = 0.0f;
    const size_t rowBase = (size_t)blockIdx.x * 256;
    for (int r = 0; r < 128; r++) {
        const float v = x[(rowBase + (size_t)r * 2 + h) * OUT_F + c];
        s += v;
        q = fmaf(v, v, q);
    }
    __shared__ float ss[256], sq[256];
    ss[t] = s; sq[t] = q;
    __syncthreads();
    if (t < 128) {
        g_psum[blockIdx.x * OUT_F + t] = ss[t] + ss[t + 128];
        g_psq [blockIdx.x * OUT_F + t] = sq[t] + sq[t + 128];
    }
}

__global__ __launch_bounds__(256) void k3b_finalize(const float* __restrict__ gamma,
                                                    const float* __restrict__ beta)
{
    __shared__ float ss[256], qq[256];
    const int c = blockIdx.x;
    const int t = threadIdx.x;
    ss[t] = g_psum[t * OUT_F + c];
    qq[t] = g_psq [t * OUT_F + c];
    __syncthreads();
    #pragma unroll
    for (int stp = 128; stp > 0; stp >>= 1) {
        if (t < stp) { ss[t] += ss[t + stp]; qq[t] += qq[t + stp]; }
        __syncthreads();
    }
    if (t == 0) {
        const float inv_n = 1.0f / (float)N_PTS;
        const float mean = ss[0] * inv_n;
        const float var  = qq[0] * inv_n - mean * mean;
        const float sc   = gamma[c] * rsqrtf(var + BN_EPS);
        g_scale[c] = sc;
        g_bias[c]  = beta[c] - mean * sc;
    }
}

__global__ __launch_bounds__(256) void k4_bnrelu(float* __restrict__ x)
{
    const int i = blockIdx.x * 256 + threadIdx.x;
    float4 v = reinterpret_cast<float4*>(x)[i];
    const int c0 = (i * 4) & 127;
    const float4 sc = *reinterpret_cast<const float4*>(g_scale + c0);
    const float4 bi = *reinterpret_cast<const float4*>(g_bias + c0);
    v.x = fmaf(v.x, sc.x, bi.x); v.x = (v.x >= 0.0f) ? v.x : NEG_SLOPE * v.x;
    v.y = fmaf(v.y, sc.y, bi.y); v.y = (v.y >= 0.0f) ? v.y : NEG_SLOPE * v.y;
    v.z = fmaf(v.z, sc.z, bi.z); v.z = (v.z >= 0.0f) ? v.z : NEG_SLOPE * v.z;
    v.w = fmaf(v.w, sc.w, bi.w); v.w = (v.w >= 0.0f) ? v.w : NEG_SLOPE * v.w;
    reinterpret_cast<float4*>(x)[i] = v;
}

// =====================================================================
extern "C" void kernel_launch(void* const* d_in, const int* in_sizes, int n_in,
                              void* d_out, int out_size)
{
    const float* qp    = (const float*)d_in[0];
    const float* sp    = (const float*)d_in[1];
    const int*   nbr   = (const int*)  d_in[2];
    const float* feat  = (const float*)d_in[3];
    const float* kpts  = (const float*)d_in[4];
    const float* Wf    = (const float*)d_in[5];
    const float* gamma = (const float*)d_in[6];
    const float* beta  = (const float*)d_in[7];
    float* out = (float*)d_out;

    cudaFuncSetAttribute(k2_gemm_mma,
                         cudaFuncAttributeMaxDynamicSharedMemorySize, K2_SMEM);

    k0_prep<<<(RDIM * OUT_F + 255) / 256, 256>>>(Wf);
    k1_weighted<<<N_PTS / 8, 256>>>(qp, sp, nbr, feat, kpts);
    k2_gemm_mma<<<N_PTS / 128, 256, K2_SMEM>>>(out);
    k3a_partial<<<256, 256>>>(out);
    k3b_finalize<<<OUT_F, 256>>>(gamma, beta);
    k4_bnrelu<<<(N_PTS * OUT_F / 4) / 256, 256>>>(out);
}